// round 14
// baseline (speedup 1.0000x reference)
#include <cuda_runtime.h>
#include <math_constants.h>

// ---------------- scratch (no allocations allowed -> __device__ globals) ----
#define MAX_N   16384
#define STRIDE  160          // padded bucket capacity; Poisson(64) max ~98
__device__ int g_sr1[MAX_N * STRIDE];   // r1 in padded per-node buckets
__device__ int g_count[MAX_N];          // per-node count (self-cleaning)

// ---------------- kernel 1: single-pass bucket build (2 edges/thread) --------
__global__ void k_build(const int* __restrict__ ratings, int n_edges) {
    int t  = blockIdx.x * blockDim.x + threadIdx.x;
    int e0 = t * 2;
    if (e0 + 1 < n_edges) {
        int4 a = ((const int4*)ratings)[t];          // two edges
        int ra = atomicAdd(&g_count[a.x], 1);
        int rb = atomicAdd(&g_count[a.z], 1);
        g_sr1[a.x * STRIDE + ra] = a.y;
        g_sr1[a.z * STRIDE + rb] = a.w;
    } else if (e0 < n_edges) {
        int2 rr = ((const int2*)ratings)[e0];
        int r = atomicAdd(&g_count[rr.x], 1);
        g_sr1[rr.x * STRIDE + r] = rr.y;
    }
}

__device__ __forceinline__ float dot4(float4 a, float4 b) {
    return a.x * b.x + a.y * b.y + a.z * b.z + a.w * b.w;
}

// ---------------- kernel 2: fused score + online softmax + gather ------------
// Block = 4 warps per node. Each warp splits into 4 groups of 8 lanes; each
// group processes one edge per step (4 edges per warp-instruction stream).
// Lane ll of a group owns dim-chunks {ll, ll+8, ll+16, ll+24} (16 dims).
// 16 independent online-softmax states per block, merged once at the end.
__global__ void k_fused(const float* __restrict__ embs,
                        float*       __restrict__ out,
                        int node_num) {
    int n    = blockIdx.x;
    int t    = threadIdx.x;
    int w    = t >> 5;
    int lane = t & 31;
    int g    = lane >> 3;          // group within warp (0..3)
    int ll   = lane & 7;           // lane within group
    int gi   = (w << 2) | g;       // global group id (0..15)

    __shared__ float4 s_emb[32];
    __shared__ float  s_ms[16], s_ss[16];
    __shared__ float4 s_accf[16][32];   // 16 groups x 128 dims

    int cnt = g_count[n];
    if (cnt == 0) {
        out[(size_t)n * 128 + t] = 0.f;
        return;
    }
    int off = n * STRIDE;

    if (t < 32) s_emb[t] = ((const float4*)(embs + (size_t)n * 128))[t];
    __syncthreads();
    float4 q0 = s_emb[ll],      q1 = s_emb[ll + 8];
    float4 q2 = s_emb[ll + 16], q3 = s_emb[ll + 24];

    float  m = -1e30f;            // finite sentinel (scores are O(+-100))
    float  s = 0.f;
    float4 a0 = make_float4(0,0,0,0), a1 = a0, a2 = a0, a3 = a0;

    const float4* embs4 = (const float4*)embs;

    // group gi handles edges gi, gi+16, gi+32, ...  (e = 4w + 16*it + g)
    int nv  = cnt - (w << 2);
    int nit = (nv > 0) ? ((nv + 15) >> 4) : 0;

#define SOFTMAX_STEP(d, u0, u1, u2, u3)                      \
    {                                                        \
        bool  up = (d) > m;                                  \
        float mn = up ? (d) : m;                             \
        float ex = __expf((up ? m : (d)) - mn);              \
        float cs = up ? ex : 1.f;                            \
        float cv = up ? 1.f : ex;                            \
        s = s * cs + cv;                                     \
        a0.x = a0.x * cs + cv * (u0).x; a0.y = a0.y * cs + cv * (u0).y; \
        a0.z = a0.z * cs + cv * (u0).z; a0.w = a0.w * cs + cv * (u0).w; \
        a1.x = a1.x * cs + cv * (u1).x; a1.y = a1.y * cs + cv * (u1).y; \
        a1.z = a1.z * cs + cv * (u1).z; a1.w = a1.w * cs + cv * (u1).w; \
        a2.x = a2.x * cs + cv * (u2).x; a2.y = a2.y * cs + cv * (u2).y; \
        a2.z = a2.z * cs + cv * (u2).z; a2.w = a2.w * cs + cv * (u2).w; \
        a3.x = a3.x * cs + cv * (u3).x; a3.y = a3.y * cs + cv * (u3).y; \
        a3.z = a3.z * cs + cv * (u3).z; a3.w = a3.w * cs + cv * (u3).w; \
        m = mn;                                              \
    }

    int it = 0;
    // ---- 2-stage pipeline: 8 edges per warp in flight ----
    for (; it + 1 < nit; it += 2) {
        int eA = (w << 2) + (it << 4) + g;
        int eB = eA + 16;
        bool okA = eA < cnt;
        bool okB = eB < cnt;
        int iA = okA ? g_sr1[off + eA] : 0;
        int iB = okB ? g_sr1[off + eB] : 0;
        const float4* rA = embs4 + (size_t)iA * 32;
        const float4* rB = embs4 + (size_t)iB * 32;
        float4 u0 = rA[ll], u1 = rA[ll + 8], u2 = rA[ll + 16], u3 = rA[ll + 24];
        float4 x0 = rB[ll], x1 = rB[ll + 8], x2 = rB[ll + 16], x3 = rB[ll + 24];
        float dA = dot4(q0,u0) + dot4(q1,u1) + dot4(q2,u2) + dot4(q3,u3);
        float dB = dot4(q0,x0) + dot4(q1,x1) + dot4(q2,x2) + dot4(q3,x3);
#pragma unroll
        for (int o = 1; o < 8; o <<= 1) {
            dA += __shfl_xor_sync(0xFFFFFFFFu, dA, o);
            dB += __shfl_xor_sync(0xFFFFFFFFu, dB, o);
        }
        dA = okA ? dA : -CUDART_INF_F;     // exp(-inf - m) = 0 -> no-op
        dB = okB ? dB : -CUDART_INF_F;
        SOFTMAX_STEP(dA, u0, u1, u2, u3)
        SOFTMAX_STEP(dB, x0, x1, x2, x3)
    }
    // ---- single-stage remainder ----
    for (; it < nit; it++) {
        int e = (w << 2) + (it << 4) + g;
        bool ok = e < cnt;
        int iA = ok ? g_sr1[off + e] : 0;
        const float4* rA = embs4 + (size_t)iA * 32;
        float4 u0 = rA[ll], u1 = rA[ll + 8], u2 = rA[ll + 16], u3 = rA[ll + 24];
        float d = dot4(q0,u0) + dot4(q1,u1) + dot4(q2,u2) + dot4(q3,u3);
#pragma unroll
        for (int o = 1; o < 8; o <<= 1) d += __shfl_xor_sync(0xFFFFFFFFu, d, o);
        d = ok ? d : -CUDART_INF_F;
        SOFTMAX_STEP(d, u0, u1, u2, u3)
    }
#undef SOFTMAX_STEP

    // ---- merge the 16 group states ----
    if (ll == 0) { s_ms[gi] = m; s_ss[gi] = s; }
    __syncthreads();
    float M = -1e30f;
#pragma unroll
    for (int j = 0; j < 16; j++) M = fmaxf(M, s_ms[j]);
    float S = 0.f;
#pragma unroll
    for (int j = 0; j < 16; j++) S += s_ss[j] * __expf(s_ms[j] - M);

    float scale = __expf(m - M);   // empty group: exp(-1e30 - M) = 0
    s_accf[gi][ll]      = make_float4(a0.x*scale, a0.y*scale, a0.z*scale, a0.w*scale);
    s_accf[gi][ll + 8]  = make_float4(a1.x*scale, a1.y*scale, a1.z*scale, a1.w*scale);
    s_accf[gi][ll + 16] = make_float4(a2.x*scale, a2.y*scale, a2.z*scale, a2.w*scale);
    s_accf[gi][ll + 24] = make_float4(a3.x*scale, a3.y*scale, a3.z*scale, a3.w*scale);
    __syncthreads();

    // thread t sums dim t across the 16 group buffers
    float num = 0.f;
#pragma unroll
    for (int j = 0; j < 16; j++) num += ((const float*)s_accf[j])[t];
    out[(size_t)n * 128 + t] = num * (1.f / S);

    // self-clean for the next launch/replay (deterministic across calls)
    if (t == 0) g_count[n] = 0;
}

// ---------------- launch -----------------------------------------------------
extern "C" void kernel_launch(void* const* d_in, const int* in_sizes, int n_in,
                              void* d_out, int out_size) {
    const float* embs    = (const float*)d_in[0];
    const int*   ratings = (const int*)d_in[1];
    float*       out     = (float*)d_out;

    int node_num = in_sizes[0] / 128;   // embs is (node_num, 128)
    int n_edges  = in_sizes[1] / 2;     // ratings is (n_edges, 2)

    int pthreads = (n_edges + 1) / 2;
    k_build<<<(pthreads + 255) / 256, 256>>>(ratings, n_edges);
    k_fused<<<node_num, 128>>>(embs, out, node_num);
}

// round 17
// speedup vs baseline: 1.1904x; 1.1904x over previous
#include <cuda_runtime.h>
#include <math_constants.h>

// ---------------- scratch (no allocations allowed -> __device__ globals) ----
#define MAX_N   16384
#define STRIDE  160          // padded bucket capacity; Poisson(64) max ~98
__device__ int g_sr1[MAX_N * STRIDE];   // r1 in padded per-node buckets
__device__ int g_count[MAX_N];          // per-node count (self-cleaning)

// ---------------- kernel 1: single-pass bucket build (2 edges/thread) --------
__global__ void k_build(const int* __restrict__ ratings, int n_edges) {
    int t  = blockIdx.x * blockDim.x + threadIdx.x;
    int e0 = t * 2;
    if (e0 + 1 < n_edges) {
        int4 a = ((const int4*)ratings)[t];          // two edges
        int ra = atomicAdd(&g_count[a.x], 1);
        int rb = atomicAdd(&g_count[a.z], 1);
        g_sr1[a.x * STRIDE + ra] = a.y;
        g_sr1[a.z * STRIDE + rb] = a.w;
    } else if (e0 < n_edges) {
        int2 rr = ((const int2*)ratings)[e0];
        int r = atomicAdd(&g_count[rr.x], 1);
        g_sr1[rr.x * STRIDE + r] = rr.y;
    }
}

__device__ __forceinline__ float dot4(float4 a, float4 b) {
    return a.x * b.x + a.y * b.y + a.z * b.z + a.w * b.w;
}

// ---------------- kernel 2: fused score + online softmax + gather ------------
// One block (4 warps) per node, warp w takes edges w, w+4, ...
// 4 edges per iteration via transpose-reduce (lane class l&3 owns edge l&3):
//   6 SHFL for all four dots, 2 SHFL for the 4-edge max, ONE exp for all four
//   weights, one rescale of (s, acc) per iteration. All exponents <= 0, so
//   self-edge scores (~chi2_128, up to ~170) cannot overflow.
__global__ void k_fused(const float* __restrict__ embs,
                        float*       __restrict__ out,
                        int node_num) {
    int n    = blockIdx.x;
    int t    = threadIdx.x;
    int w    = t >> 5;
    int lane = t & 31;

    __shared__ float4 s_emb[32];
    __shared__ float  s_m[4], s_s[4];
    __shared__ float4 s_acc[4][32];

    int cnt = g_count[n];
    if (cnt == 0) {
        out[(size_t)n * 128 + t] = 0.f;
        return;
    }
    int off = n * STRIDE;

    if (t < 32) s_emb[t] = ((const float4*)(embs + (size_t)n * 128))[t];
    __syncthreads();
    float4 q = s_emb[lane];

    float  m   = -1e30f;     // finite sentinel
    float  s   = 0.f;
    float4 acc = make_float4(0.f, 0.f, 0.f, 0.f);

    bool o1 = lane & 1;
    bool o2 = lane & 2;

    int i = w;
    // ---- 4 edges per iteration ----
    for (; i + 12 < cnt; i += 16) {
        int i0 = g_sr1[off + i];
        int i1 = g_sr1[off + i + 4];
        int i2 = g_sr1[off + i + 8];
        int i3 = g_sr1[off + i + 12];
        float4 v0 = ((const float4*)(embs + (size_t)i0 * 128))[lane];
        float4 v1 = ((const float4*)(embs + (size_t)i1 * 128))[lane];
        float4 v2 = ((const float4*)(embs + (size_t)i2 * 128))[lane];
        float4 v3 = ((const float4*)(embs + (size_t)i3 * 128))[lane];
        float p0 = dot4(q, v0);
        float p1 = dot4(q, v1);
        float p2 = dot4(q, v2);
        float p3 = dot4(q, v3);

        // transpose-reduce: lane class (l&3) ends up holding d_{l&3}
        float hi01 = o1 ? p0 : p1, lo01 = o1 ? p1 : p0;
        float hi23 = o1 ? p2 : p3, lo23 = o1 ? p3 : p2;
        float r01 = lo01 + __shfl_xor_sync(0xFFFFFFFFu, hi01, 1);
        float r23 = lo23 + __shfl_xor_sync(0xFFFFFFFFu, hi23, 1);
        float hiB = o2 ? r01 : r23, loB = o2 ? r23 : r01;
        float rB  = loB + __shfl_xor_sync(0xFFFFFFFFu, hiB, 2);
        rB += __shfl_xor_sync(0xFFFFFFFFu, rB, 4);
        rB += __shfl_xor_sync(0xFFFFFFFFu, rB, 8);
        rB += __shfl_xor_sync(0xFFFFFFFFu, rB, 16);

        // 4-edge max -> every lane
        float mx = rB;
        mx = fmaxf(mx, __shfl_xor_sync(0xFFFFFFFFu, mx, 1));
        mx = fmaxf(mx, __shfl_xor_sync(0xFFFFFFFFu, mx, 2));

        float mn = fmaxf(m, mx);
        float cs = __expf(m - mn);             // carry rescale (first iter: 0)
        float we = __expf(rB - mn);            // lane l holds w_{l&3}; exp<=0
        float w0 = __shfl_sync(0xFFFFFFFFu, we, 0);
        float w1 = __shfl_sync(0xFFFFFFFFu, we, 1);
        float w2 = __shfl_sync(0xFFFFFFFFu, we, 2);
        float w3 = __shfl_sync(0xFFFFFFFFu, we, 3);

        s = s * cs + ((w0 + w1) + (w2 + w3));
        acc.x = acc.x * cs + (w0 * v0.x + w1 * v1.x + w2 * v2.x + w3 * v3.x);
        acc.y = acc.y * cs + (w0 * v0.y + w1 * v1.y + w2 * v2.y + w3 * v3.y);
        acc.z = acc.z * cs + (w0 * v0.z + w1 * v1.z + w2 * v2.z + w3 * v3.z);
        acc.w = acc.w * cs + (w0 * v0.w + w1 * v1.w + w2 * v2.w + w3 * v3.w);
        m = mn;
    }
    // ---- scalar tail: per-edge online update ----
    for (; i < cnt; i += 4) {
        int r1 = g_sr1[off + i];
        float4 v = ((const float4*)(embs + (size_t)r1 * 128))[lane];
        float d = dot4(q, v);
#pragma unroll
        for (int o = 16; o; o >>= 1) d += __shfl_xor_sync(0xFFFFFFFFu, d, o);
        float mn = fmaxf(m, d);
        float cs = __expf(m - mn);
        float wt = __expf(d - mn);
        s = s * cs + wt;
        acc.x = acc.x * cs + wt * v.x;
        acc.y = acc.y * cs + wt * v.y;
        acc.z = acc.z * cs + wt * v.z;
        acc.w = acc.w * cs + wt * v.w;
        m = mn;
    }

    // ---- combine the 4 warps (log-sum-exp merge) ----
    if (lane == 0) { s_m[w] = m; s_s[w] = s; }
    __syncthreads();
    float M = fmaxf(fmaxf(s_m[0], s_m[1]), fmaxf(s_m[2], s_m[3]));  // finite
    float scale = __expf(m - M);               // idle warp: exp(-1e30-M)=0
    s_acc[w][lane] = make_float4(acc.x * scale, acc.y * scale,
                                 acc.z * scale, acc.w * scale);
    __syncthreads();

    float S = 0.f;
#pragma unroll
    for (int j = 0; j < 4; j++) S += s_s[j] * __expf(s_m[j] - M);

    const float* f0 = (const float*)&s_acc[0][0];
    const float* f1 = (const float*)&s_acc[1][0];
    const float* f2 = (const float*)&s_acc[2][0];
    const float* f3 = (const float*)&s_acc[3][0];
    float num = (f0[t] + f1[t]) + (f2[t] + f3[t]);
    out[(size_t)n * 128 + t] = num * (1.f / S);

    // self-clean for the next launch/replay (deterministic across calls)
    if (t == 0) g_count[n] = 0;
}

// ---------------- launch -----------------------------------------------------
extern "C" void kernel_launch(void* const* d_in, const int* in_sizes, int n_in,
                              void* d_out, int out_size) {
    const float* embs    = (const float*)d_in[0];
    const int*   ratings = (const int*)d_in[1];
    float*       out     = (float*)d_out;

    int node_num = in_sizes[0] / 128;   // embs is (node_num, 128)
    int n_edges  = in_sizes[1] / 2;     // ratings is (n_edges, 2)

    int pthreads = (n_edges + 1) / 2;
    k_build<<<(pthreads + 255) / 256, 256>>>(ratings, n_edges);
    k_fused<<<node_num, 128>>>(embs, out, node_num);
}